// round 4
// baseline (speedup 1.0000x reference)
#include <cuda_runtime.h>
#include <math.h>

#define EPSV 1e-5f
#define RS 144   // padded row stride for rel rows 0..15 (phase B)
#define SSW 68   // ss row stride (diag stride 69 odd -> conflict-free)

// 64 MiB scratch: qkv in layout [n][o][h][w], o in [0,256)
static __device__ float g_qkv[16 * 256 * 64 * 64];

// ---------------- f32x2 packed-FMA helpers (Blackwell FFMA2) ----------------
__device__ __forceinline__ unsigned long long pk2(float x, float y) {
    unsigned long long r;
    asm("mov.b64 %0, {%1, %2};" : "=l"(r) : "f"(x), "f"(y));
    return r;
}
__device__ __forceinline__ void fma2(unsigned long long& d,
                                     unsigned long long a, unsigned long long b) {
    asm("fma.rn.f32x2 %0, %1, %2, %0;" : "+l"(d) : "l"(a), "l"(b));
}
__device__ __forceinline__ float2 upk2(unsigned long long v) {
    float2 r;
    asm("mov.b64 {%0, %1}, %2;" : "=f"(r.x), "=f"(r.y) : "l"(v));
    return r;
}

// ---------------------------------------------------------------------------
// Kernel 1: qkv GEMM+BN. Tile 128o x 128hw, 256 threads, 8x8 microtile, f32x2.
// Grid: (hw-tiles=32, o-tiles=2, n=16)
// ---------------------------------------------------------------------------
__global__ __launch_bounds__(256) void qkv_kernel(
    const float* __restrict__ x, const float* __restrict__ w,
    const float* __restrict__ bnq)
{
    __shared__ float wsT[16][136];  // [c-chunk][o], transposed W
    __shared__ float xs[16][128];   // [c-chunk][hw]

    const int n   = blockIdx.z;
    const int o0  = blockIdx.y * 128;
    const int hw0 = blockIdx.x * 128;
    const int tid = threadIdx.x;
    const int tx  = tid & 15, ty = tid >> 4;

    unsigned long long acc[8][4];   // [o][hw-pair]; pairs 0,1: tx*4; 2,3: 64+tx*4
#pragma unroll
    for (int a = 0; a < 8; a++)
#pragma unroll
        for (int p = 0; p < 4; p++) acc[a][p] = 0ull;

    const float* xb = x + (size_t)n * 128 * 4096;
    const int oo = tid >> 1, qh = (tid & 1) * 8;  // W loader
    const int colA = tx * 4, colB = 64 + tx * 4;

    for (int c0 = 0; c0 < 128; c0 += 16) {
        {   // W tile 128o x 16c, transposed
            const float* wr = &w[(o0 + oo) * 128 + c0 + qh];
            float4 w1 = *(const float4*)wr;
            float4 w2 = *(const float4*)(wr + 4);
            wsT[qh + 0][oo] = w1.x; wsT[qh + 1][oo] = w1.y;
            wsT[qh + 2][oo] = w1.z; wsT[qh + 3][oo] = w1.w;
            wsT[qh + 4][oo] = w2.x; wsT[qh + 5][oo] = w2.y;
            wsT[qh + 6][oo] = w2.z; wsT[qh + 7][oo] = w2.w;
        }
        {   // x tile 16c x 128hw
            const float* xr = &xb[(size_t)(c0 + ty) * 4096 + hw0];
            *(float4*)&xs[ty][colA] = *(const float4*)&xr[colA];
            *(float4*)&xs[ty][colB] = *(const float4*)&xr[colB];
        }
        __syncthreads();
#pragma unroll
        for (int kk = 0; kk < 16; kk++) {
            float4 aA = *(const float4*)&wsT[kk][ty * 8];
            float4 aB = *(const float4*)&wsT[kk][ty * 8 + 4];
            float4 bA = *(const float4*)&xs[kk][colA];
            float4 bB = *(const float4*)&xs[kk][colB];
            unsigned long long bp[4];
            bp[0] = pk2(bA.x, bA.y); bp[1] = pk2(bA.z, bA.w);
            bp[2] = pk2(bB.x, bB.y); bp[3] = pk2(bB.z, bB.w);
            float av[8] = {aA.x, aA.y, aA.z, aA.w, aB.x, aB.y, aB.z, aB.w};
#pragma unroll
            for (int a = 0; a < 8; a++) {
                unsigned long long a2 = pk2(av[a], av[a]);
                fma2(acc[a][0], a2, bp[0]);
                fma2(acc[a][1], a2, bp[1]);
                fma2(acc[a][2], a2, bp[2]);
                fma2(acc[a][3], a2, bp[3]);
            }
        }
        __syncthreads();
    }

    float* ob = g_qkv + (size_t)n * 256 * 4096;
#pragma unroll
    for (int a = 0; a < 8; a++) {
        int o = o0 + ty * 8 + a;
        float as = bnq[o] * rsqrtf(bnq[768 + o] + EPSV);
        float bs = bnq[256 + o] - as * bnq[512 + o];
        float2 u0 = upk2(acc[a][0]), u1 = upk2(acc[a][1]);
        float2 u2 = upk2(acc[a][2]), u3 = upk2(acc[a][3]);
        float4 r1, r2;
        r1.x = as * u0.x + bs; r1.y = as * u0.y + bs;
        r1.z = as * u1.x + bs; r1.w = as * u1.y + bs;
        r2.x = as * u2.x + bs; r2.y = as * u2.y + bs;
        r2.z = as * u3.x + bs; r2.w = as * u3.y + bs;
        float* orow = &ob[(size_t)o * 4096 + hw0];
        *(float4*)&orow[colA] = r1;
        *(float4*)&orow[colB] = r2;
    }
}

// ---------------------------------------------------------------------------
// Kernel 2: fused attention per (n, g, 4 consecutive w). Grid (16,8,16), 256t.
// ---------------------------------------------------------------------------
__global__ __launch_bounds__(256, 2) void attn_kernel(
    const float* __restrict__ relative,
    const float* __restrict__ bns,   // (4,24)
    const float* __restrict__ bno,   // (4,256)
    float* __restrict__ out)
{
    extern __shared__ float sm[];
    float* rel   = sm;               // 16*RS           = 2304
    float* relT  = rel + 16 * RS;    // 127*16          = 2032
    float* sq    = relT + 2032;      // 4*32*64         = 8192
    float* ss    = sq + 8192;        // 64*SSW          = 4352
    float* vT    = ss + 64 * SSW;    // 64*20           = 1280
    float* part  = vT + 1280;        // 4*64*17         = 4352
    float* svred = part + 4352;      // 64*17           = 1088
    float* invr  = svred + 1088;     // 64
    float* bnc   = invr + 64;        // 48 (A0,A1,B x16)
    float* obuf  = bnc + 48;         // 16*64*4         = 4096

    const int g   = blockIdx.y;
    const int n   = blockIdx.z;
    const int w0  = blockIdx.x * 4;
    const int tid = threadIdx.x;

    // rel rows 0..15 (q_emb/k_emb) with stride RS
    for (int idx = tid; idx < 16 * 127; idx += 256) {
        int c = idx / 127, d = idx - c * 127;
        rel[c * RS + d] = relative[idx];
    }
    // relT[d][c] = relative[16+c][d]  (v_emb transposed, 64B rows)
    for (int idx = tid; idx < 127 * 16; idx += 256) {
        int d = idx >> 4, c = idx & 15;
        relT[idx] = relative[(16 + c) * 127 + d];
    }
    // qkv tile for 4 b's: float4 over w
    const float* qb = g_qkv + ((size_t)n * 256 + g * 32) * 4096 + w0;
    for (int idx = tid; idx < 2048; idx += 256) {
        float4 v = *(const float4*)&qb[(size_t)idx * 64];
        sq[idx]        = v.x;
        sq[2048 + idx] = v.y;
        sq[4096 + idx] = v.z;
        sq[6144 + idx] = v.w;
    }
    // bn_out affine per cc -> smem
    if (tid < 16) {
        int ch0 = 2 * (g * 16 + tid), ch1 = ch0 + 1;
        float a0 = bno[ch0] * rsqrtf(bno[768 + ch0] + EPSV);
        float a1 = bno[ch1] * rsqrtf(bno[768 + ch1] + EPSV);
        bnc[tid]      = a0;
        bnc[16 + tid] = a1;
        bnc[32 + tid] = (bno[256 + ch0] - a0 * bno[512 + ch0])
                      + (bno[256 + ch1] - a1 * bno[512 + ch1]);
    }

    // bn_sim affine constants
    float a_qk, a_qr, a_kr, bsum;
    {
        int c0 = g, c1 = 8 + g, c2 = 16 + g;
        a_qk = bns[c0] * rsqrtf(bns[72 + c0] + EPSV);
        a_qr = bns[c1] * rsqrtf(bns[72 + c1] + EPSV);
        a_kr = bns[c2] * rsqrtf(bns[72 + c2] + EPSV);
        bsum = (bns[24 + c0] - a_qk * bns[48 + c0])
             + (bns[24 + c1] - a_qr * bns[48 + c1])
             + (bns[24 + c2] - a_kr * bns[48 + c2]);
    }

    const int ty = tid >> 4, tx = tid & 15;
    const int i0 = ty * 4, j0 = tx * 4;        // phase B microtile
    const int wrp = tid >> 5, ln = tid & 31;   // phase C mapping
    const int ih = wrp & 1, qt = wrp >> 1;     // i-half, j/d quarter
    const int ic = ih * 32 + ln;               // phase C lane's i
    const int i2 = tid >> 2, qq = tid & 3;     // reduce mapping
    __syncthreads();

    for (int wi = 0; wi < 4; wi++) {
        const float* q_ = sq + wi * 2048;

        // ---- Phase B: S[i,j] ----
        float acc[4][4];
#pragma unroll
        for (int a = 0; a < 4; a++)
#pragma unroll
            for (int b = 0; b < 4; b++) acc[a][b] = bsum;

        const int db  = i0 - j0 + 60;
        const int db2 = 120 - db;
#pragma unroll
        for (int c = 0; c < 8; c++) {
            float4 q4 = *(const float4*)&q_[c * 64 + i0];
            float4 k4 = *(const float4*)&q_[(8 + c) * 64 + j0];
            float qv[4] = {q4.x, q4.y, q4.z, q4.w};
            float kv[4] = {k4.x, k4.y, k4.z, k4.w};
            const float* rq = rel + c * RS + db;
            const float* rk = rel + (8 + c) * RS + db2;
            float4 rqa = *(const float4*)rq;
            float4 rqb = *(const float4*)(rq + 4);
            float4 rka = *(const float4*)rk;
            float4 rkb = *(const float4*)(rk + 4);
            float rqv[8] = {rqa.x, rqa.y, rqa.z, rqa.w, rqb.x, rqb.y, rqb.z, rqb.w};
            float rkv[8] = {rka.x, rka.y, rka.z, rka.w, rkb.x, rkb.y, rkb.z, rkb.w};
            float kb[4];
#pragma unroll
            for (int b = 0; b < 4; b++) kb[b] = a_kr * kv[b];
#pragma unroll
            for (int a = 0; a < 4; a++) {
                float qa  = a_qk * qv[a];
                float qbr = a_qr * qv[a];
#pragma unroll
                for (int b = 0; b < 4; b++) {
                    acc[a][b] += qa  * kv[b];
                    acc[a][b] += qbr * rqv[3 + a - b];
                    acc[a][b] += kb[b] * rkv[3 + b - a];
                }
            }
        }
#pragma unroll
        for (int a = 0; a < 4; a++)
#pragma unroll
            for (int b = 0; b < 4; b++)
                ss[(i0 + a) * SSW + j0 + b] = acc[a][b];
        __syncthreads();

        // ---- Softmax over j (+ build vT for this wi) ----
        {
            int r = tid >> 2, qd = tid & 3;
            float* row = ss + r * SSW + qd * 16;
            float m = row[0];
#pragma unroll
            for (int t = 1; t < 16; t++) m = fmaxf(m, row[t]);
            m = fmaxf(m, __shfl_xor_sync(0xffffffffu, m, 1));
            m = fmaxf(m, __shfl_xor_sync(0xffffffffu, m, 2));
            float s = 0.f;
#pragma unroll
            for (int t = 0; t < 16; t++) {
                float e = __expf(row[t] - m);
                row[t] = e; s += e;
            }
            s += __shfl_xor_sync(0xffffffffu, s, 1);
            s += __shfl_xor_sync(0xffffffffu, s, 2);
            if (qd == 0) invr[r] = 1.0f / s;
        }
        for (int t = tid; t < 1024; t += 256) {   // vT[j][cc] = v[cc][j]
            int cc = t >> 6, j = t & 63;
            vT[j * 20 + cc] = q_[(16 + cc) * 64 + j];
        }
        __syncthreads();

        // ---- Pass A: sv[i][cc], warp=(ih,jq), P read once per (i,j) ----
        {
            float sv[16];
#pragma unroll
            for (int c = 0; c < 16; c++) sv[c] = 0.f;
            const float* ssr = ss + ic * SSW;
#pragma unroll
            for (int j4 = 0; j4 < 4; j4++) {
                int jb = qt * 16 + j4 * 4;
                float4 p4 = *(const float4*)&ssr[jb];
                float pv[4] = {p4.x, p4.y, p4.z, p4.w};
#pragma unroll
                for (int jj = 0; jj < 4; jj++) {
                    const float* vr = vT + (jb + jj) * 20;
#pragma unroll
                    for (int cq = 0; cq < 4; cq++) {
                        float4 v4 = *(const float4*)&vr[cq * 4];
                        sv[cq * 4 + 0] += pv[jj] * v4.x;
                        sv[cq * 4 + 1] += pv[jj] * v4.y;
                        sv[cq * 4 + 2] += pv[jj] * v4.z;
                        sv[cq * 4 + 3] += pv[jj] * v4.w;
                    }
                }
            }
            float* pa = part + qt * 1088 + ic * 17;
#pragma unroll
            for (int c = 0; c < 16; c++) pa[c] = sv[c];
        }
        __syncthreads();

        // ---- Reduce A -> svred ----
        {
#pragma unroll
            for (int k = 0; k < 4; k++) {
                int cc = qq * 4 + k;
                float s = part[i2 * 17 + cc] + part[1088 + i2 * 17 + cc]
                        + part[2176 + i2 * 17 + cc] + part[3264 + i2 * 17 + cc];
                svred[i2 * 17 + cc] = s;
            }
        }
        __syncthreads();

        // ---- Pass B: se[i][cc] over diagonals d=i-j (rel broadcast) ----
        {
            float se[16];
#pragma unroll
            for (int c = 0; c < 16; c++) se[c] = 0.f;
            const int dbase = ih * 32 + qt * 24 - 63;
#pragma unroll 4
            for (int t = 0; t < 24; t++) {
                int d = dbase + t;
                if (d > 63) break;
                int j = ic - d;
                bool val = (unsigned)j < 64u;
                float p = val ? ss[ic * SSW + j] : 0.f;
                const float* rr = relT + (d + 63) * 16;
#pragma unroll
                for (int cq = 0; cq < 4; cq++) {
                    float4 r4 = *(const float4*)&rr[cq * 4];
                    se[cq * 4 + 0] += p * r4.x;
                    se[cq * 4 + 1] += p * r4.y;
                    se[cq * 4 + 2] += p * r4.z;
                    se[cq * 4 + 3] += p * r4.w;
                }
            }
            float* pb = part + qt * 1088 + ic * 17;
#pragma unroll
            for (int c = 0; c < 16; c++) pb[c] = se[c];
        }
        __syncthreads();

        // ---- Reduce B + BN_out + pair-sum -> obuf ----
        {
            float ir = invr[i2];
#pragma unroll
            for (int k = 0; k < 4; k++) {
                int cc = qq * 4 + k;
                float se_s = part[i2 * 17 + cc] + part[1088 + i2 * 17 + cc]
                           + part[2176 + i2 * 17 + cc] + part[3264 + i2 * 17 + cc];
                float sv_s = svred[i2 * 17 + cc];
                obuf[(cc * 64 + i2) * 4 + wi] =
                    ir * (bnc[cc] * sv_s + bnc[16 + cc] * se_s) + bnc[32 + cc];
            }
        }
        __syncthreads();
    }

    // ---- Final coalesced write ----
    float* ob = out + ((size_t)(n * 128 + g * 16)) * 4096 + w0;
    for (int idx = tid; idx < 1024; idx += 256) {
        *(float4*)&ob[(size_t)idx * 64] = *(const float4*)&obuf[idx * 4];
    }
}

// ---------------------------------------------------------------------------
extern "C" void kernel_launch(void* const* d_in, const int* in_sizes, int n_in,
                              void* d_out, int out_size)
{
    const float* x    = (const float*)d_in[0];
    const float* w    = (const float*)d_in[1];
    const float* relv = (const float*)d_in[2];
    const float* bnq  = (const float*)d_in[3];
    const float* bns  = (const float*)d_in[4];
    const float* bno  = (const float*)d_in[5];
    float* out = (float*)d_out;

    const int SMEM = (2304 + 2032 + 8192 + 4352 + 1280 + 4352 + 1088 + 64 + 48 + 4096) * 4;
    cudaFuncSetAttribute(attn_kernel,
                         cudaFuncAttributeMaxDynamicSharedMemorySize, SMEM);

    qkv_kernel<<<dim3(32, 2, 16), 256>>>(x, w, bnq);
    attn_kernel<<<dim3(16, 8, 16), 256, SMEM>>>(relv, bns, bno, out);
}